// round 3
// baseline (speedup 1.0000x reference)
#include <cuda_runtime.h>
#include <math.h>

#define BQ 4
#define NV 4096
#define NK 128
#define NC 128
#define NSPLIT 16

// ---------------- scratch (device globals; no cudaMalloc allowed) ----------
__device__ float g_x    [BQ*NV*NC];
__device__ float g_GXe  [BQ*NV*NK];
__device__ float g_GYe  [BQ*NV*NK];
__device__ float g_xdiff[BQ*NV*NC];
__device__ float g_gx   [BQ*NV*NC];
__device__ float g_gy   [BQ*NV*NC];
__device__ float g_gfeat[BQ*NV*NC];
__device__ float g_h0   [BQ*NV*NC];
__device__ float g_h1   [BQ*NV*NC];
__device__ float g_specp[NSPLIT*BQ*NK*NC];
__device__ float g_y    [BQ*NK*NC];

// ---------------- 1) input linear: x = x_in @ Wf + bf ----------------------
__global__ __launch_bounds__(128) void k_input(const float* __restrict__ x_in,
                                               const float* __restrict__ Wf,
                                               const float* __restrict__ bf) {
    int bv = blockIdx.x;            // 0..B*V-1
    int c  = threadIdx.x;           // 0..127
    __shared__ float xs[16];
    if (c < 16) xs[c] = x_in[bv*16 + c];
    __syncthreads();
    float acc = bf[c];
#pragma unroll
    for (int j = 0; j < 16; j++) acc = fmaf(xs[j], Wf[j*NC + c], acc);
    g_x[(size_t)bv*NC + c] = acc;
}

// ---------------- 2) one-time big SGEMM: GXe = gradX @ evecs ----------------
// 128x128 block tile, BK=8, 256 threads, 8x8 per-thread microtile.
__global__ __launch_bounds__(256) void k_grad_pre(const float* __restrict__ gradX,
                                                  const float* __restrict__ gradY,
                                                  const float* __restrict__ evecs) {
    const int b = blockIdx.y;
    const float* A  = (blockIdx.z == 0 ? gradX : gradY) + (size_t)b*NV*NV;
    const float* Bm = evecs + (size_t)b*NV*NK;
    float* C = (blockIdx.z == 0 ? g_GXe : g_GYe) + (size_t)b*NV*NK;

    __shared__ float As[8][132];   // padded to kill store conflicts
    __shared__ float Bs[8][128];

    const int tid = threadIdx.x;
    const int tx = tid & 15, ty = tid >> 4;
    const int row0 = blockIdx.x * 128;

    const int arow = tid >> 1;           // 0..127
    const int acol = (tid & 1) * 4;      // 0 or 4
    const int brow = tid >> 5;           // 0..7
    const int bcol = (tid & 31) * 4;

    float acc[8][8] = {};

    for (int k0 = 0; k0 < NV; k0 += 8) {
        float4 av = *(const float4*)&A[(size_t)(row0 + arow)*NV + k0 + acol];
        As[acol+0][arow] = av.x; As[acol+1][arow] = av.y;
        As[acol+2][arow] = av.z; As[acol+3][arow] = av.w;
        *(float4*)&Bs[brow][bcol] = *(const float4*)&Bm[(size_t)(k0 + brow)*NK + bcol];
        __syncthreads();
#pragma unroll
        for (int kk = 0; kk < 8; kk++) {
            float a[8], w[8];
#pragma unroll
            for (int i = 0; i < 8; i++) a[i] = As[kk][ty*8+i];
#pragma unroll
            for (int j = 0; j < 8; j++) w[j] = Bs[kk][tx*8+j];
#pragma unroll
            for (int i = 0; i < 8; i++)
#pragma unroll
                for (int j = 0; j < 8; j++)
                    acc[i][j] = fmaf(a[i], w[j], acc[i][j]);
        }
        __syncthreads();
    }
#pragma unroll
    for (int i = 0; i < 8; i++) {
        int r = row0 + ty*8 + i;
#pragma unroll
        for (int j = 0; j < 8; j += 4) {
            float4 v = make_float4(acc[i][j], acc[i][j+1], acc[i][j+2], acc[i][j+3]);
            *(float4*)&C[(size_t)r*NK + tx*8 + j] = v;
        }
    }
}

// ---------------- 3) x_spec partial: evecs^T @ (x*mass), split-K ------------
__global__ __launch_bounds__(256) void k_spec(const float* __restrict__ evecs,
                                              const float* __restrict__ mass) {
    const int s = blockIdx.x, b = blockIdx.y;
    const float* E = evecs + (size_t)b*NV*NK;
    const float* X = g_x   + (size_t)b*NV*NC;
    const float* M = mass  + (size_t)b*NV;

    __shared__ float Es[8][128];
    __shared__ float Xs[8][128];

    const int tid = threadIdx.x;
    const int tx = tid & 15, ty = tid >> 4;
    const int lrow = tid >> 5;          // 0..7
    const int lcol = (tid & 31) * 4;
    const int v0 = s * (NV / NSPLIT);   // 256-wide chunk

    float acc[8][8] = {};

    for (int vt = 0; vt < NV/NSPLIT; vt += 8) {
        int vb = v0 + vt + lrow;
        *(float4*)&Es[lrow][lcol] = *(const float4*)&E[(size_t)vb*NK + lcol];
        float4 xv = *(const float4*)&X[(size_t)vb*NC + lcol];
        float mv = M[vb];
        xv.x *= mv; xv.y *= mv; xv.z *= mv; xv.w *= mv;
        *(float4*)&Xs[lrow][lcol] = xv;
        __syncthreads();
#pragma unroll
        for (int vv = 0; vv < 8; vv++) {
            float e[8], xr[8];
#pragma unroll
            for (int i = 0; i < 8; i++) e[i]  = Es[vv][ty*8+i];
#pragma unroll
            for (int j = 0; j < 8; j++) xr[j] = Xs[vv][tx*8+j];
#pragma unroll
            for (int i = 0; i < 8; i++)
#pragma unroll
                for (int j = 0; j < 8; j++)
                    acc[i][j] = fmaf(e[i], xr[j], acc[i][j]);
        }
        __syncthreads();
    }
    float* P = g_specp + ((size_t)(s*BQ + b)*NK)*NC;
#pragma unroll
    for (int i = 0; i < 8; i++)
#pragma unroll
        for (int j = 0; j < 8; j += 4) {
            float4 v = make_float4(acc[i][j], acc[i][j+1], acc[i][j+2], acc[i][j+3]);
            *(float4*)&P[(size_t)(ty*8+i)*NC + tx*8 + j] = v;
        }
}

// ---------------- 4) reduce partials + diffusion coefficients ---------------
__global__ __launch_bounds__(256) void k_scale(const float* __restrict__ evals,
                                               const float* __restrict__ t, int iblk) {
    int idx = blockIdx.x * blockDim.x + threadIdx.x;  // B*K*C = 65536
    int c = idx & 127;
    int k = (idx >> 7) & 127;
    int b = idx >> 14;
    float ti = fmaxf(t[iblk*NC + c], 1e-8f);
    float coef = expf(-evals[b*NK + k] * ti);
    float ssum = 0.f;
#pragma unroll
    for (int p = 0; p < NSPLIT; p++)
        ssum += g_specp[((size_t)(p*BQ + b)*NK + k)*NC + c];
    g_y[idx] = coef * ssum;
}

// ---------------- 5) generic GEMM: C = act(sum_chunks A_i@W_i + bias)[+res] -
// 64 rows x 128 cols per block, 256 threads, 8x4 microtile.
__global__ __launch_bounds__(256) void k_gemm(const float* A0, const float* A1, const float* A2,
                                              int nchunks, long long strideA,
                                              const float* __restrict__ W, long long strideW,
                                              const float* __restrict__ bias,
                                              const float* resid, long long strideR,
                                              float* C, long long strideC, int act) {
    const int b = blockIdx.y;
    const int row0 = blockIdx.x * 64;

    __shared__ float AsT[16][64];
    __shared__ float Ws[16][128];

    const int tid = threadIdx.x;
    const int tc = tid & 31, tr = tid >> 5;
    const int larow = tid >> 2;          // 0..63
    const int lacol = (tid & 3) * 4;     // 0,4,8,12

    float acc[8][4] = {};
    const float* Achunks[3] = {A0, A1, A2};

    for (int ci = 0; ci < nchunks; ci++) {
        const float* A  = Achunks[ci] + (size_t)b * strideA;
        const float* Wc = W + (size_t)b * strideW + (size_t)ci * 128 * 128;
        for (int k0 = 0; k0 < 128; k0 += 16) {
            float4 av = *(const float4*)&A[(size_t)(row0 + larow)*128 + k0 + lacol];
            AsT[lacol+0][larow] = av.x; AsT[lacol+1][larow] = av.y;
            AsT[lacol+2][larow] = av.z; AsT[lacol+3][larow] = av.w;
#pragma unroll
            for (int l = 0; l < 2; l++) {
                int idx = tid + l*256;
                int r  = idx >> 5;            // 0..15
                int c4 = (idx & 31) * 4;
                *(float4*)&Ws[r][c4] = *(const float4*)&Wc[(size_t)(k0 + r)*128 + c4];
            }
            __syncthreads();
#pragma unroll
            for (int kk = 0; kk < 16; kk++) {
                float4 wv = *(const float4*)&Ws[kk][tc*4];
#pragma unroll
                for (int r = 0; r < 8; r++) {
                    float a = AsT[kk][tr*8 + r];
                    acc[r][0] = fmaf(a, wv.x, acc[r][0]);
                    acc[r][1] = fmaf(a, wv.y, acc[r][1]);
                    acc[r][2] = fmaf(a, wv.z, acc[r][2]);
                    acc[r][3] = fmaf(a, wv.w, acc[r][3]);
                }
            }
            __syncthreads();
        }
    }
    // epilogue
    float4 bv = make_float4(0.f, 0.f, 0.f, 0.f);
    if (bias) bv = *(const float4*)&bias[tc*4];
#pragma unroll
    for (int r = 0; r < 8; r++) {
        int row = row0 + tr*8 + r;
        float4 v = make_float4(acc[r][0] + bv.x, acc[r][1] + bv.y,
                               acc[r][2] + bv.z, acc[r][3] + bv.w);
        if (resid) {
            float4 rr = *(const float4*)&resid[(size_t)b*strideR + (size_t)row*128 + tc*4];
            v.x += rr.x; v.y += rr.y; v.z += rr.z; v.w += rr.w;
        }
        if (act == 1) {
            v.x = fmaxf(v.x, 0.f); v.y = fmaxf(v.y, 0.f);
            v.z = fmaxf(v.z, 0.f); v.w = fmaxf(v.w, 0.f);
        }
        *(float4*)&C[(size_t)b*strideC + (size_t)row*128 + tc*4] = v;
    }
}

// ---------------- 6) complex linear + tanh gradient features ----------------
__global__ __launch_bounds__(128) void k_cgrad(const float* __restrict__ Are,
                                               const float* __restrict__ Aim, int iblk) {
    const int b  = blockIdx.y;
    const int v0 = blockIdx.x * 16;
    const int c  = threadIdx.x;   // 0..127

    __shared__ float gxs[16][128];
    __shared__ float gys[16][128];

    const float* GX = g_gx + (size_t)b*NV*NC + (size_t)v0*NC;
    const float* GY = g_gy + (size_t)b*NV*NC + (size_t)v0*NC;
#pragma unroll
    for (int r = 0; r < 16; r++) {
        gxs[r][c] = GX[r*128 + c];
        gys[r][c] = GY[r*128 + c];
    }
    __syncthreads();

    const float* ar_p = Are + (size_t)iblk*128*128;
    const float* ai_p = Aim + (size_t)iblk*128*128;

    float br[16], bi[16];
#pragma unroll
    for (int v = 0; v < 16; v++) { br[v] = 0.f; bi[v] = 0.f; }

    for (int k = 0; k < 128; k++) {
        float ar = ar_p[k*128 + c];
        float ai = ai_p[k*128 + c];
#pragma unroll
        for (int v = 0; v < 16; v++) {
            float gx = gxs[v][k], gy = gys[v][k];
            br[v] = fmaf(gx, ar, br[v]); br[v] = fmaf(-gy, ai, br[v]);
            bi[v] = fmaf(gy, ar, bi[v]); bi[v] = fmaf( gx, ai, bi[v]);
        }
    }
    float* GF = g_gfeat + (size_t)b*NV*NC + (size_t)v0*NC;
#pragma unroll
    for (int v = 0; v < 16; v++) {
        float z = gxs[v][c]*br[v] + gys[v][c]*bi[v];
        GF[v*128 + c] = tanhf(z);
    }
}

// ---------------- host orchestration ---------------------------------------
extern "C" void kernel_launch(void* const* d_in, const int* in_sizes, int n_in,
                              void* d_out, int out_size) {
    const float* x_in  = (const float*)d_in[0];
    const float* mass  = (const float*)d_in[1];
    const float* evals = (const float*)d_in[2];
    const float* evecs = (const float*)d_in[3];
    const float* gradX = (const float*)d_in[4];
    const float* gradY = (const float*)d_in[5];
    const float* Wf    = (const float*)d_in[6];
    const float* bf    = (const float*)d_in[7];
    const float* Wl    = (const float*)d_in[8];
    const float* bl    = (const float*)d_in[9];
    const float* t     = (const float*)d_in[10];
    const float* Are   = (const float*)d_in[11];
    const float* Aim   = (const float*)d_in[12];
    const float* W0    = (const float*)d_in[13];
    const float* b0    = (const float*)d_in[14];
    const float* W1    = (const float*)d_in[15];
    const float* b1    = (const float*)d_in[16];
    const float* W2    = (const float*)d_in[17];
    const float* b2    = (const float*)d_in[18];
    float* out = (float*)d_out;

    float *p_x, *p_GXe, *p_GYe, *p_xdiff, *p_gx, *p_gy, *p_gfeat, *p_h0, *p_h1, *p_y;
    cudaGetSymbolAddress((void**)&p_x,     g_x);
    cudaGetSymbolAddress((void**)&p_GXe,   g_GXe);
    cudaGetSymbolAddress((void**)&p_GYe,   g_GYe);
    cudaGetSymbolAddress((void**)&p_xdiff, g_xdiff);
    cudaGetSymbolAddress((void**)&p_gx,    g_gx);
    cudaGetSymbolAddress((void**)&p_gy,    g_gy);
    cudaGetSymbolAddress((void**)&p_gfeat, g_gfeat);
    cudaGetSymbolAddress((void**)&p_h0,    g_h0);
    cudaGetSymbolAddress((void**)&p_h1,    g_h1);
    cudaGetSymbolAddress((void**)&p_y,     g_y);

    const long long sVC = (long long)NV * NC;   // per-batch stride for [B,V,128]
    const long long sKC = (long long)NK * NC;   // per-batch stride for y

    // x = x_in @ Wf + bf
    k_input<<<BQ*NV, 128>>>(x_in, Wf, bf);

    // one-time: GXe = gradX @ evecs, GYe = gradY @ evecs
    k_grad_pre<<<dim3(NV/128, BQ, 2), 256>>>(gradX, gradY, evecs);

    for (int i = 0; i < 4; i++) {
        // spectral: y = exp(-evals*t_i) * (evecs^T (x*mass))
        k_spec<<<dim3(NSPLIT, BQ), 256>>>(evecs, mass);
        k_scale<<<(BQ*NK*NC)/256, 256>>>(evals, t, i);

        // x_diff = evecs @ y ; gx = GXe @ y ; gy = GYe @ y
        k_gemm<<<dim3(NV/64, BQ), 256>>>(evecs, nullptr, nullptr, 1, sVC,
                                         p_y, sKC, nullptr, nullptr, 0,
                                         p_xdiff, sVC, 0);
        k_gemm<<<dim3(NV/64, BQ), 256>>>(p_GXe, nullptr, nullptr, 1, sVC,
                                         p_y, sKC, nullptr, nullptr, 0,
                                         p_gx, sVC, 0);
        k_gemm<<<dim3(NV/64, BQ), 256>>>(p_GYe, nullptr, nullptr, 1, sVC,
                                         p_y, sKC, nullptr, nullptr, 0,
                                         p_gy, sVC, 0);

        // gfeat = tanh(gx*(gx@Are - gy@Aim) + gy*(gy@Are + gx@Aim))
        k_cgrad<<<dim3(NV/16, BQ), 128>>>(Are, Aim, i);

        // MLP: h0 = relu([x|x_diff|gfeat] @ W0 + b0)
        k_gemm<<<dim3(NV/64, BQ), 256>>>(p_x, p_xdiff, p_gfeat, 3, sVC,
                                         W0 + (size_t)i*384*128, 0, b0 + i*128,
                                         nullptr, 0, p_h0, sVC, 1);
        // h1 = relu(h0 @ W1 + b1)
        k_gemm<<<dim3(NV/64, BQ), 256>>>(p_h0, nullptr, nullptr, 1, sVC,
                                         W1 + (size_t)i*128*128, 0, b1 + i*128,
                                         nullptr, 0, p_h1, sVC, 1);
        // x = x + (h1 @ W2 + b2)
        k_gemm<<<dim3(NV/64, BQ), 256>>>(p_h1, nullptr, nullptr, 1, sVC,
                                         W2 + (size_t)i*128*128, 0, b2 + i*128,
                                         p_x, sVC, p_x, sVC, 0);
    }

    // out = x @ Wl + bl
    k_gemm<<<dim3(NV/64, BQ), 256>>>(p_x, nullptr, nullptr, 1, sVC,
                                     Wl, 0, bl, nullptr, 0, out, sVC, 0);
}

// round 5
// speedup vs baseline: 1.3594x; 1.3594x over previous
#include <cuda_runtime.h>
#include <cuda_bf16.h>
#include <math.h>
#include <stdint.h>

#define BQ 4
#define NV 4096
#define NK 128
#define NC 128
#define NSPLIT 16

// ---------------- scratch (device globals; no cudaMalloc allowed) ----------
__device__ float g_x    [BQ*NV*NC];
__device__ float g_GXe  [BQ*NV*NK];
__device__ float g_GYe  [BQ*NV*NK];
__device__ float g_xdiff[BQ*NV*NC];
__device__ float g_gx   [BQ*NV*NC];
__device__ float g_gy   [BQ*NV*NC];
__device__ float g_gfeat[BQ*NV*NC];
__device__ float g_h0   [BQ*NV*NC];
__device__ float g_h1   [BQ*NV*NC];
__device__ float g_specp[NSPLIT*BQ*NK*NC];
__device__ float g_y    [BQ*NK*NC];
__device__ __nv_bfloat16 g_eTh[BQ*NK*NV];   // evecs^T split hi  [b][n][v]
__device__ __nv_bfloat16 g_eTl[BQ*NK*NV];   // evecs^T split lo

// ---------------- arch-agnostic PTX helpers (no sm_103a-gated ops!) ---------
__device__ __forceinline__ uint32_t smem_u32(const void* p) {
    uint32_t a;
    asm("{ .reg .u64 t; cvta.to.shared.u64 t, %1; cvt.u32.u64 %0, t; }"
        : "=r"(a) : "l"(p));
    return a;
}
__device__ __forceinline__ void ldmatrix_x4(uint32_t* r, uint32_t addr) {
    asm volatile("ldmatrix.sync.aligned.m8n8.x4.shared.b16 {%0,%1,%2,%3}, [%4];"
                 : "=r"(r[0]), "=r"(r[1]), "=r"(r[2]), "=r"(r[3]) : "r"(addr));
}
__device__ __forceinline__ void ldmatrix_x2(uint32_t* r, uint32_t addr) {
    asm volatile("ldmatrix.sync.aligned.m8n8.x2.shared.b16 {%0,%1}, [%2];"
                 : "=r"(r[0]), "=r"(r[1]) : "r"(addr));
}
__device__ __forceinline__ void mma_bf16(float* c, const uint32_t* a, const uint32_t* b) {
    asm volatile("mma.sync.aligned.m16n8k16.row.col.f32.bf16.bf16.f32 "
                 "{%0,%1,%2,%3}, {%4,%5,%6,%7}, {%8,%9}, {%0,%1,%2,%3};"
                 : "+f"(c[0]), "+f"(c[1]), "+f"(c[2]), "+f"(c[3])
                 : "r"(a[0]), "r"(a[1]), "r"(a[2]), "r"(a[3]), "r"(b[0]), "r"(b[1]));
}

// ---------------- 0) transpose + bf16 split of evecs ------------------------
__global__ __launch_bounds__(256) void k_evT(const float* __restrict__ evecs) {
    __shared__ float tile[32][33];
    const int b = blockIdx.z;
    const int v0 = blockIdx.x * 32, n0 = blockIdx.y * 32;
    const int tx = threadIdx.x, ty = threadIdx.y;   // 32 x 8
#pragma unroll
    for (int j = 0; j < 32; j += 8)
        tile[ty + j][tx] = evecs[(size_t)b*NV*NK + (size_t)(v0 + ty + j)*NK + n0 + tx];
    __syncthreads();
#pragma unroll
    for (int j = 0; j < 32; j += 8) {
        float val = tile[tx][ty + j];                // evecs[v0+tx][n0+ty+j]
        __nv_bfloat16 hi = __float2bfloat16(val);
        __nv_bfloat16 lo = __float2bfloat16(val - __bfloat162float(hi));
        size_t o = (size_t)b*NK*NV + (size_t)(n0 + ty + j)*NV + v0 + tx;
        g_eTh[o] = hi;
        g_eTl[o] = lo;
    }
}

// ---------------- 1) input linear: x = x_in @ Wf + bf ----------------------
__global__ __launch_bounds__(128) void k_input(const float* __restrict__ x_in,
                                               const float* __restrict__ Wf,
                                               const float* __restrict__ bf) {
    int bv = blockIdx.x;
    int c  = threadIdx.x;
    __shared__ float xs[16];
    if (c < 16) xs[c] = x_in[bv*16 + c];
    __syncthreads();
    float acc = bf[c];
#pragma unroll
    for (int j = 0; j < 16; j++) acc = fmaf(xs[j], Wf[j*NC + c], acc);
    g_x[(size_t)bv*NC + c] = acc;
}

// ---------------- 2) HMMA grad precompute: GXe/GYe = grad @ evecs -----------
// 128x128 tile/CTA, 8 warps (2x4), 64x32 per warp, bf16x3 decomposition,
// mma.sync.m16n8k16 with fp32 accumulators. K streamed in 64-wide chunks.
// smem: Ah(16K) Al(16K) Bh(16K) Bl(16K) = 64 KB, XOR-swizzled 128B rows.
#define GM_SMEM 65536

__global__ __launch_bounds__(256, 1) void k_grad_mma(const float* __restrict__ gradX,
                                                     const float* __restrict__ gradY) {
    extern __shared__ char smem[];
    char* Ah = smem;
    char* Al = smem + 16384;
    char* Bh = smem + 32768;
    char* Bl = smem + 49152;

    const int tid = threadIdx.x, wid = tid >> 5, lane = tid & 31;
    const int b = blockIdx.y;
    const float* A = (blockIdx.z == 0 ? gradX : gradY) + (size_t)b*NV*NV;
    float*       C = (blockIdx.z == 0 ? g_GXe : g_GYe) + (size_t)b*NV*NK;
    const char* eh = (const char*)(g_eTh + (size_t)b*NK*NV);
    const char* el = (const char*)(g_eTl + (size_t)b*NK*NV);
    const int row0 = blockIdx.x * 128;
    const int wm = (wid >> 2) * 64;   // warp M offset: 0 / 64
    const int wn = (wid & 3) * 32;    // warp N offset: 0..96

    const uint32_t sAh = smem_u32(Ah), sAl = smem_u32(Al);
    const uint32_t sBh = smem_u32(Bh), sBl = smem_u32(Bl);

    // ldmatrix lane address components
    const int a_r = lane & 15;              // row within 16-row m-tile
    const int a_s = (lane >> 4) * 16;       // k-halves (16B)
    const int b_r = lane & 7;               // n within 8-col n-tile
    const int b_s = ((lane >> 3) & 1) * 16; // k-halves (16B), lanes 0-15 used

    float acc[4][4][4];
#pragma unroll
    for (int m = 0; m < 4; m++)
#pragma unroll
        for (int n = 0; n < 4; n++)
#pragma unroll
            for (int j = 0; j < 4; j++) acc[m][n][j] = 0.f;

    for (int c = 0; c < NV/64; c++) {
        __syncthreads();   // previous chunk's MMA reads done before overwrite
        // --- A chunk [128 rows x 64 k]: fp32 -> bf16 hi/lo, swizzled smem ---
#pragma unroll
        for (int i = 0; i < 8; i++) {
            int idx = i*256 + tid;
            int r  = idx >> 4;          // 0..127
            int k4 = idx & 15;          // float4 within row
            float4 v = *(const float4*)&A[(size_t)(row0 + r)*NV + (size_t)c*64 + k4*4];
            __nv_bfloat16 h0 = __float2bfloat16(v.x), h1 = __float2bfloat16(v.y);
            __nv_bfloat16 h2 = __float2bfloat16(v.z), h3 = __float2bfloat16(v.w);
            __nv_bfloat16 l0 = __float2bfloat16(v.x - __bfloat162float(h0));
            __nv_bfloat16 l1 = __float2bfloat16(v.y - __bfloat162float(h1));
            __nv_bfloat16 l2 = __float2bfloat16(v.z - __bfloat162float(h2));
            __nv_bfloat16 l3 = __float2bfloat16(v.w - __bfloat162float(h3));
            uint2 hp, lp;
            hp.x = (uint32_t)__bfloat16_as_ushort(h0) | ((uint32_t)__bfloat16_as_ushort(h1) << 16);
            hp.y = (uint32_t)__bfloat16_as_ushort(h2) | ((uint32_t)__bfloat16_as_ushort(h3) << 16);
            lp.x = (uint32_t)__bfloat16_as_ushort(l0) | ((uint32_t)__bfloat16_as_ushort(l1) << 16);
            lp.y = (uint32_t)__bfloat16_as_ushort(l2) | ((uint32_t)__bfloat16_as_ushort(l3) << 16);
            uint32_t off = (uint32_t)(r*128) + (((uint32_t)(k4*8)) ^ (uint32_t)((r & 7)*16));
            *(uint2*)(Ah + off) = hp;
            *(uint2*)(Al + off) = lp;
        }
        // --- B chunk [128 n x 64 k] bf16 hi/lo from pre-split evecs^T ---
#pragma unroll
        for (int i = 0; i < 4; i++) {
            int idx = i*256 + tid;
            int n  = idx >> 3;          // 0..127
            int c4 = idx & 7;           // 16B unit within row
            size_t gb = (size_t)n*NV*2 + (size_t)c*128 + (size_t)c4*16;
            uint4 vh = *(const uint4*)(eh + gb);
            uint4 vl = *(const uint4*)(el + gb);
            uint32_t off = (uint32_t)(n*128) + (((uint32_t)(c4*16)) ^ (uint32_t)((n & 7)*16));
            *(uint4*)(Bh + off) = vh;
            *(uint4*)(Bl + off) = vl;
        }
        __syncthreads();

        // --- MMA: 4 k16 steps; per step: hi*hi + hi*lo + lo*hi ---
#pragma unroll
        for (int ks = 0; ks < 4; ks++) {
            uint32_t ah[4][4], al[4][4];
#pragma unroll
            for (int m = 0; m < 4; m++) {
                int r = wm + m*16 + a_r;
                uint32_t kb = (uint32_t)(ks*32 + a_s) ^ (uint32_t)((r & 7)*16);
                uint32_t off = (uint32_t)(r*128) + kb;
                ldmatrix_x4(ah[m], sAh + off);
                ldmatrix_x4(al[m], sAl + off);
            }
#pragma unroll
            for (int n = 0; n < 4; n++) {
                int nr = wn + n*8 + b_r;
                uint32_t kb = (uint32_t)(ks*32 + b_s) ^ (uint32_t)((nr & 7)*16);
                uint32_t off = (uint32_t)(nr*128) + kb;
                uint32_t bh[2], bl[2];
                ldmatrix_x2(bh, sBh + off);
                ldmatrix_x2(bl, sBl + off);
#pragma unroll
                for (int m = 0; m < 4; m++) {
                    mma_bf16(acc[m][n], ah[m], bh);
                    mma_bf16(acc[m][n], ah[m], bl);
                    mma_bf16(acc[m][n], al[m], bh);
                }
            }
        }
    }

    // --- writeback: thread t holds rows (t/4, t/4+8), cols 2*(t%4)+{0,1} ---
    const int cr = lane >> 2;
    const int cc = (lane & 3) * 2;
#pragma unroll
    for (int m = 0; m < 4; m++) {
        int r = row0 + wm + m*16 + cr;
#pragma unroll
        for (int n = 0; n < 4; n++) {
            int col = wn + n*8 + cc;
            *(float2*)&C[(size_t)r*NK + col]       = make_float2(acc[m][n][0], acc[m][n][1]);
            *(float2*)&C[(size_t)(r + 8)*NK + col] = make_float2(acc[m][n][2], acc[m][n][3]);
        }
    }
}

// ---------------- 3) x_spec partial: evecs^T @ (x*mass), split-K ------------
__global__ __launch_bounds__(256) void k_spec(const float* __restrict__ evecs,
                                              const float* __restrict__ mass) {
    const int s = blockIdx.x, b = blockIdx.y;
    const float* E = evecs + (size_t)b*NV*NK;
    const float* X = g_x   + (size_t)b*NV*NC;
    const float* M = mass  + (size_t)b*NV;

    __shared__ float Es[8][128];
    __shared__ float Xs[8][128];

    const int tid = threadIdx.x;
    const int tx = tid & 15, ty = tid >> 4;
    const int lrow = tid >> 5;
    const int lcol = (tid & 31) * 4;
    const int v0 = s * (NV / NSPLIT);

    float acc[8][8] = {};

    for (int vt = 0; vt < NV/NSPLIT; vt += 8) {
        int vb = v0 + vt + lrow;
        *(float4*)&Es[lrow][lcol] = *(const float4*)&E[(size_t)vb*NK + lcol];
        float4 xv = *(const float4*)&X[(size_t)vb*NC + lcol];
        float mv = M[vb];
        xv.x *= mv; xv.y *= mv; xv.z *= mv; xv.w *= mv;
        *(float4*)&Xs[lrow][lcol] = xv;
        __syncthreads();
#pragma unroll
        for (int vv = 0; vv < 8; vv++) {
            float e[8], xr[8];
#pragma unroll
            for (int i = 0; i < 8; i++) e[i]  = Es[vv][ty*8+i];
#pragma unroll
            for (int j = 0; j < 8; j++) xr[j] = Xs[vv][tx*8+j];
#pragma unroll
            for (int i = 0; i < 8; i++)
#pragma unroll
                for (int j = 0; j < 8; j++)
                    acc[i][j] = fmaf(e[i], xr[j], acc[i][j]);
        }
        __syncthreads();
    }
    float* P = g_specp + ((size_t)(s*BQ + b)*NK)*NC;
#pragma unroll
    for (int i = 0; i < 8; i++)
#pragma unroll
        for (int j = 0; j < 8; j += 4) {
            float4 v = make_float4(acc[i][j], acc[i][j+1], acc[i][j+2], acc[i][j+3]);
            *(float4*)&P[(size_t)(ty*8+i)*NC + tx*8 + j] = v;
        }
}

// ---------------- 4) reduce partials + diffusion coefficients ---------------
__global__ __launch_bounds__(256) void k_scale(const float* __restrict__ evals,
                                               const float* __restrict__ t, int iblk) {
    int idx = blockIdx.x * blockDim.x + threadIdx.x;
    int c = idx & 127;
    int k = (idx >> 7) & 127;
    int b = idx >> 14;
    float ti = fmaxf(t[iblk*NC + c], 1e-8f);
    float coef = expf(-evals[b*NK + k] * ti);
    float ssum = 0.f;
#pragma unroll
    for (int p = 0; p < NSPLIT; p++)
        ssum += g_specp[((size_t)(p*BQ + b)*NK + k)*NC + c];
    g_y[idx] = coef * ssum;
}

// ---------------- 5) generic GEMM: C = act(sum_chunks A_i@W_i + bias)[+res] -
__global__ __launch_bounds__(256) void k_gemm(const float* A0, const float* A1, const float* A2,
                                              int nchunks, long long strideA,
                                              const float* __restrict__ W, long long strideW,
                                              const float* __restrict__ bias,
                                              const float* resid, long long strideR,
                                              float* C, long long strideC, int act) {
    const int b = blockIdx.y;
    const int row0 = blockIdx.x * 64;

    __shared__ float AsT[16][64];
    __shared__ float Ws[16][128];

    const int tid = threadIdx.x;
    const int tc = tid & 31, tr = tid >> 5;
    const int larow = tid >> 2;
    const int lacol = (tid & 3) * 4;

    float acc[8][4] = {};
    const float* Achunks[3] = {A0, A1, A2};

    for (int ci = 0; ci < nchunks; ci++) {
        const float* A  = Achunks[ci] + (size_t)b * strideA;
        const float* Wc = W + (size_t)b * strideW + (size_t)ci * 128 * 128;
        for (int k0 = 0; k0 < 128; k0 += 16) {
            float4 av = *(const float4*)&A[(size_t)(row0 + larow)*128 + k0 + lacol];
            AsT[lacol+0][larow] = av.x; AsT[lacol+1][larow] = av.y;
            AsT[lacol+2][larow] = av.z; AsT[lacol+3][larow] = av.w;
#pragma unroll
            for (int l = 0; l < 2; l++) {
                int idx = tid + l*256;
                int r  = idx >> 5;
                int c4 = (idx & 31) * 4;
                *(float4*)&Ws[r][c4] = *(const float4*)&Wc[(size_t)(k0 + r)*128 + c4];
            }
            __syncthreads();
#pragma unroll
            for (int kk = 0; kk < 16; kk++) {
                float4 wv = *(const float4*)&Ws[kk][tc*4];
#pragma unroll
                for (int r = 0; r < 8; r++) {
                    float a = AsT[kk][tr*8 + r];
                    acc[r][0] = fmaf(a, wv.x, acc[r][0]);
                    acc[r][1] = fmaf(a, wv.y, acc[r][1]);
                    acc[r][2] = fmaf(a, wv.z, acc[r][2]);
                    acc[r][3] = fmaf(a, wv.w, acc[r][3]);
                }
            }
            __syncthreads();
        }
    }
    float4 bv = make_float4(0.f, 0.f, 0.f, 0.f);
    if (bias) bv = *(const float4*)&bias[tc*4];
#pragma unroll
    for (int r = 0; r < 8; r++) {
        int row = row0 + tr*8 + r;
        float4 v = make_float4(acc[r][0] + bv.x, acc[r][1] + bv.y,
                               acc[r][2] + bv.z, acc[r][3] + bv.w);
        if (resid) {
            float4 rr = *(const float4*)&resid[(size_t)b*strideR + (size_t)row*128 + tc*4];
            v.x += rr.x; v.y += rr.y; v.z += rr.z; v.w += rr.w;
        }
        if (act == 1) {
            v.x = fmaxf(v.x, 0.f); v.y = fmaxf(v.y, 0.f);
            v.z = fmaxf(v.z, 0.f); v.w = fmaxf(v.w, 0.f);
        }
        *(float4*)&C[(size_t)b*strideC + (size_t)row*128 + tc*4] = v;
    }
}

// ---------------- 6) complex linear + tanh gradient features ----------------
__global__ __launch_bounds__(128) void k_cgrad(const float* __restrict__ Are,
                                               const float* __restrict__ Aim, int iblk) {
    const int b  = blockIdx.y;
    const int v0 = blockIdx.x * 16;
    const int c  = threadIdx.x;

    __shared__ float gxs[16][128];
    __shared__ float gys[16][128];

    const float* GX = g_gx + (size_t)b*NV*NC + (size_t)v0*NC;
    const float* GY = g_gy + (size_t)b*NV*NC + (size_t)v0*NC;
#pragma unroll
    for (int r = 0; r < 16; r++) {
        gxs[r][c] = GX[r*128 + c];
        gys[r][c] = GY[r*128 + c];
    }
    __syncthreads();

    const float* ar_p = Are + (size_t)iblk*128*128;
    const float* ai_p = Aim + (size_t)iblk*128*128;

    float br[16], bi[16];
#pragma unroll
    for (int v = 0; v < 16; v++) { br[v] = 0.f; bi[v] = 0.f; }

    for (int k = 0; k < 128; k++) {
        float ar = ar_p[k*128 + c];
        float ai = ai_p[k*128 + c];
#pragma unroll
        for (int v = 0; v < 16; v++) {
            float gx = gxs[v][k], gy = gys[v][k];
            br[v] = fmaf(gx, ar, br[v]); br[v] = fmaf(-gy, ai, br[v]);
            bi[v] = fmaf(gy, ar, bi[v]); bi[v] = fmaf( gx, ai, bi[v]);
        }
    }
    float* GF = g_gfeat + (size_t)b*NV*NC + (size_t)v0*NC;
#pragma unroll
    for (int v = 0; v < 16; v++) {
        float z = gxs[v][c]*br[v] + gys[v][c]*bi[v];
        GF[v*128 + c] = tanhf(z);
    }
}

// ---------------- host orchestration ---------------------------------------
extern "C" void kernel_launch(void* const* d_in, const int* in_sizes, int n_in,
                              void* d_out, int out_size) {
    const float* x_in  = (const float*)d_in[0];
    const float* mass  = (const float*)d_in[1];
    const float* evals = (const float*)d_in[2];
    const float* evecs = (const float*)d_in[3];
    const float* gradX = (const float*)d_in[4];
    const float* gradY = (const float*)d_in[5];
    const float* Wf    = (const float*)d_in[6];
    const float* bf    = (const float*)d_in[7];
    const float* Wl    = (const float*)d_in[8];
    const float* bl    = (const float*)d_in[9];
    const float* t     = (const float*)d_in[10];
    const float* Are   = (const float*)d_in[11];
    const float* Aim   = (const float*)d_in[12];
    const float* W0    = (const float*)d_in[13];
    const float* b0    = (const float*)d_in[14];
    const float* W1    = (const float*)d_in[15];
    const float* b1    = (const float*)d_in[16];
    const float* W2    = (const float*)d_in[17];
    const float* b2    = (const float*)d_in[18];
    float* out = (float*)d_out;

    float *p_x, *p_xdiff, *p_gx, *p_gy, *p_gfeat, *p_h0, *p_h1, *p_y, *p_GXe, *p_GYe;
    cudaGetSymbolAddress((void**)&p_x,     g_x);
    cudaGetSymbolAddress((void**)&p_GXe,   g_GXe);
    cudaGetSymbolAddress((void**)&p_GYe,   g_GYe);
    cudaGetSymbolAddress((void**)&p_xdiff, g_xdiff);
    cudaGetSymbolAddress((void**)&p_gx,    g_gx);
    cudaGetSymbolAddress((void**)&p_gy,    g_gy);
    cudaGetSymbolAddress((void**)&p_gfeat, g_gfeat);
    cudaGetSymbolAddress((void**)&p_h0,    g_h0);
    cudaGetSymbolAddress((void**)&p_h1,    g_h1);
    cudaGetSymbolAddress((void**)&p_y,     g_y);

    cudaFuncSetAttribute(k_grad_mma, cudaFuncAttributeMaxDynamicSharedMemorySize, GM_SMEM);

    const long long sVC = (long long)NV * NC;
    const long long sKC = (long long)NK * NC;

    // x = x_in @ Wf + bf
    k_input<<<BQ*NV, 128>>>(x_in, Wf, bf);

    // evecs^T bf16 hi/lo split, then HMMA GXe/GYe = grad @ evecs
    k_evT<<<dim3(NV/32, NK/32, BQ), dim3(32, 8)>>>(evecs);
    k_grad_mma<<<dim3(NV/128, BQ, 2), 256, GM_SMEM>>>(gradX, gradY);

    for (int i = 0; i < 4; i++) {
        k_spec<<<dim3(NSPLIT, BQ), 256>>>(evecs, mass);
        k_scale<<<(BQ*NK*NC)/256, 256>>>(evals, t, i);

        k_gemm<<<dim3(NV/64, BQ), 256>>>(evecs, nullptr, nullptr, 1, sVC,
                                         p_y, sKC, nullptr, nullptr, 0,
                                         p_xdiff, sVC, 0);
        k_gemm<<<dim3(NV/64, BQ), 256>>>(p_GXe, nullptr, nullptr, 1, sVC,
                                         p_y, sKC, nullptr, nullptr, 0,
                                         p_gx, sVC, 0);
        k_gemm<<<dim3(NV/64, BQ), 256>>>(p_GYe, nullptr, nullptr, 1, sVC,
                                         p_y, sKC, nullptr, nullptr, 0,
                                         p_gy, sVC, 0);

        k_cgrad<<<dim3(NV/16, BQ), 128>>>(Are, Aim, i);

        k_gemm<<<dim3(NV/64, BQ), 256>>>(p_x, p_xdiff, p_gfeat, 3, sVC,
                                         W0 + (size_t)i*384*128, 0, b0 + i*128,
                                         nullptr, 0, p_h0, sVC, 1);
        k_gemm<<<dim3(NV/64, BQ), 256>>>(p_h0, nullptr, nullptr, 1, sVC,
                                         W1 + (size_t)i*128*128, 0, b1 + i*128,
                                         nullptr, 0, p_h1, sVC, 1);
        k_gemm<<<dim3(NV/64, BQ), 256>>>(p_h1, nullptr, nullptr, 1, sVC,
                                         W2 + (size_t)i*128*128, 0, b2 + i*128,
                                         p_x, sVC, p_x, sVC, 0);
    }

    k_gemm<<<dim3(NV/64, BQ), 256>>>(p_x, nullptr, nullptr, 1, sVC,
                                     Wl, 0, bl, nullptr, 0, out, sVC, 0);
}

// round 7
// speedup vs baseline: 1.7777x; 1.3077x over previous
#include <cuda_runtime.h>
#include <cuda_bf16.h>
#include <math.h>
#include <stdint.h>

#define BQ 4
#define NV 4096
#define NK 128
#define NC 128
#define NSPLIT 32

// ---------------- scratch (device globals; no cudaMalloc allowed) ----------
__device__ float g_x    [BQ*NV*NC];
__device__ float g_GXe  [BQ*NV*NK];
__device__ float g_GYe  [BQ*NV*NK];
__device__ float g_gfeat[BQ*NV*NC];
__device__ float g_specp[NSPLIT*BQ*NK*NC];
__device__ float g_y    [BQ*NK*NC];
__device__ __nv_bfloat16 g_eTh[BQ*NK*NV];   // evecs^T split hi  [b][n][v]
__device__ __nv_bfloat16 g_eTl[BQ*NK*NV];   // evecs^T split lo

// ---------------- arch-agnostic PTX helpers ---------------------------------
__device__ __forceinline__ uint32_t smem_u32(const void* p) {
    uint32_t a;
    asm("{ .reg .u64 t; cvta.to.shared.u64 t, %1; cvt.u32.u64 %0, t; }"
        : "=r"(a) : "l"(p));
    return a;
}
__device__ __forceinline__ void ldmatrix_x4(uint32_t* r, uint32_t addr) {
    asm volatile("ldmatrix.sync.aligned.m8n8.x4.shared.b16 {%0,%1,%2,%3}, [%4];"
                 : "=r"(r[0]), "=r"(r[1]), "=r"(r[2]), "=r"(r[3]) : "r"(addr));
}
__device__ __forceinline__ void ldmatrix_x2(uint32_t* r, uint32_t addr) {
    asm volatile("ldmatrix.sync.aligned.m8n8.x2.shared.b16 {%0,%1}, [%2];"
                 : "=r"(r[0]), "=r"(r[1]) : "r"(addr));
}
__device__ __forceinline__ void mma_bf16(float* c, const uint32_t* a, const uint32_t* b) {
    asm volatile("mma.sync.aligned.m16n8k16.row.col.f32.bf16.bf16.f32 "
                 "{%0,%1,%2,%3}, {%4,%5,%6,%7}, {%8,%9}, {%0,%1,%2,%3};"
                 : "+f"(c[0]), "+f"(c[1]), "+f"(c[2]), "+f"(c[3])
                 : "r"(a[0]), "r"(a[1]), "r"(a[2]), "r"(a[3]), "r"(b[0]), "r"(b[1]));
}

// ---------------- 0) transpose + bf16 split of evecs ------------------------
__global__ __launch_bounds__(256) void k_evT(const float* __restrict__ evecs) {
    __shared__ float tile[32][33];
    const int b = blockIdx.z;
    const int v0 = blockIdx.x * 32, n0 = blockIdx.y * 32;
    const int tx = threadIdx.x, ty = threadIdx.y;   // 32 x 8
#pragma unroll
    for (int j = 0; j < 32; j += 8)
        tile[ty + j][tx] = evecs[(size_t)b*NV*NK + (size_t)(v0 + ty + j)*NK + n0 + tx];
    __syncthreads();
#pragma unroll
    for (int j = 0; j < 32; j += 8) {
        float val = tile[tx][ty + j];
        __nv_bfloat16 hi = __float2bfloat16(val);
        __nv_bfloat16 lo = __float2bfloat16(val - __bfloat162float(hi));
        size_t o = (size_t)b*NK*NV + (size_t)(n0 + ty + j)*NV + v0 + tx;
        g_eTh[o] = hi;
        g_eTl[o] = lo;
    }
}

// ---------------- 1) input linear: x = x_in @ Wf + bf ----------------------
__global__ __launch_bounds__(128) void k_input(const float* __restrict__ x_in,
                                               const float* __restrict__ Wf,
                                               const float* __restrict__ bf) {
    int bv = blockIdx.x;
    int c  = threadIdx.x;
    __shared__ float xs[16];
    if (c < 16) xs[c] = x_in[bv*16 + c];
    __syncthreads();
    float acc = bf[c];
#pragma unroll
    for (int j = 0; j < 16; j++) acc = fmaf(xs[j], Wf[j*NC + c], acc);
    g_x[(size_t)bv*NC + c] = acc;
}

// ---------------- 2) HMMA grad precompute with register prefetch ------------
#define GM_SMEM 65536

__global__ __launch_bounds__(256, 1) void k_grad_mma(const float* __restrict__ gradX,
                                                     const float* __restrict__ gradY) {
    extern __shared__ char smem[];
    char* Ah = smem;
    char* Al = smem + 16384;
    char* Bh = smem + 32768;
    char* Bl = smem + 49152;

    const int tid = threadIdx.x, wid = tid >> 5, lane = tid & 31;
    const int b = blockIdx.y;
    const float* A = (blockIdx.z == 0 ? gradX : gradY) + (size_t)b*NV*NV;
    float*       C = (blockIdx.z == 0 ? g_GXe : g_GYe) + (size_t)b*NV*NK;
    const char* eh = (const char*)(g_eTh + (size_t)b*NK*NV);
    const char* el = (const char*)(g_eTl + (size_t)b*NK*NV);
    const int row0 = blockIdx.x * 128;
    const int wm = (wid >> 2) * 64;
    const int wn = (wid & 3) * 32;

    const uint32_t sAh = smem_u32(Ah), sAl = smem_u32(Al);
    const uint32_t sBh = smem_u32(Bh), sBl = smem_u32(Bl);

    const int a_r = lane & 15;
    const int a_s = (lane >> 4) * 16;
    const int b_r = lane & 7;
    const int b_s = ((lane >> 3) & 1) * 16;

    float acc[4][4][4];
#pragma unroll
    for (int m = 0; m < 4; m++)
#pragma unroll
        for (int n = 0; n < 4; n++)
#pragma unroll
            for (int j = 0; j < 4; j++) acc[m][n][j] = 0.f;

    float4 aReg[8];
    uint4  bhReg[4], blReg[4];

    // prefetch chunk 0
#pragma unroll
    for (int i = 0; i < 8; i++) {
        int idx = i*256 + tid;
        int r  = idx >> 4;
        int k4 = idx & 15;
        aReg[i] = *(const float4*)&A[(size_t)(row0 + r)*NV + k4*4];
    }
#pragma unroll
    for (int i = 0; i < 4; i++) {
        int idx = i*256 + tid;
        int n  = idx >> 3;
        int c4 = idx & 7;
        size_t gb = (size_t)n*NV*2 + (size_t)c4*16;
        bhReg[i] = *(const uint4*)(eh + gb);
        blReg[i] = *(const uint4*)(el + gb);
    }

    for (int c = 0; c < NV/64; c++) {
        // --- store chunk c regs -> smem (convert A to bf16 hi/lo) ---
#pragma unroll
        for (int i = 0; i < 8; i++) {
            int idx = i*256 + tid;
            int r  = idx >> 4;
            int k4 = idx & 15;
            float4 v = aReg[i];
            __nv_bfloat16 h0 = __float2bfloat16(v.x), h1 = __float2bfloat16(v.y);
            __nv_bfloat16 h2 = __float2bfloat16(v.z), h3 = __float2bfloat16(v.w);
            __nv_bfloat16 l0 = __float2bfloat16(v.x - __bfloat162float(h0));
            __nv_bfloat16 l1 = __float2bfloat16(v.y - __bfloat162float(h1));
            __nv_bfloat16 l2 = __float2bfloat16(v.z - __bfloat162float(h2));
            __nv_bfloat16 l3 = __float2bfloat16(v.w - __bfloat162float(h3));
            uint2 hp, lp;
            hp.x = (uint32_t)__bfloat16_as_ushort(h0) | ((uint32_t)__bfloat16_as_ushort(h1) << 16);
            hp.y = (uint32_t)__bfloat16_as_ushort(h2) | ((uint32_t)__bfloat16_as_ushort(h3) << 16);
            lp.x = (uint32_t)__bfloat16_as_ushort(l0) | ((uint32_t)__bfloat16_as_ushort(l1) << 16);
            lp.y = (uint32_t)__bfloat16_as_ushort(l2) | ((uint32_t)__bfloat16_as_ushort(l3) << 16);
            uint32_t off = (uint32_t)(r*128) + (((uint32_t)(k4*8)) ^ (uint32_t)((r & 7)*16));
            *(uint2*)(Ah + off) = hp;
            *(uint2*)(Al + off) = lp;
        }
#pragma unroll
        for (int i = 0; i < 4; i++) {
            int idx = i*256 + tid;
            int n  = idx >> 3;
            int c4 = idx & 7;
            uint32_t off = (uint32_t)(n*128) + (((uint32_t)(c4*16)) ^ (uint32_t)((n & 7)*16));
            *(uint4*)(Bh + off) = bhReg[i];
            *(uint4*)(Bl + off) = blReg[i];
        }
        __syncthreads();

        // --- prefetch chunk c+1 (clamped; LDG latency hidden by MMA) ---
        {
            int cn = (c + 1 < NV/64) ? c + 1 : c;
#pragma unroll
            for (int i = 0; i < 8; i++) {
                int idx = i*256 + tid;
                int r  = idx >> 4;
                int k4 = idx & 15;
                aReg[i] = *(const float4*)&A[(size_t)(row0 + r)*NV + (size_t)cn*64 + k4*4];
            }
#pragma unroll
            for (int i = 0; i < 4; i++) {
                int idx = i*256 + tid;
                int n  = idx >> 3;
                int c4 = idx & 7;
                size_t gb = (size_t)n*NV*2 + (size_t)cn*128 + (size_t)c4*16;
                bhReg[i] = *(const uint4*)(eh + gb);
                blReg[i] = *(const uint4*)(el + gb);
            }
        }

        // --- MMA on chunk c ---
#pragma unroll
        for (int ks = 0; ks < 4; ks++) {
            uint32_t ah[4][4], al[4][4];
#pragma unroll
            for (int m = 0; m < 4; m++) {
                int r = wm + m*16 + a_r;
                uint32_t kb = (uint32_t)(ks*32 + a_s) ^ (uint32_t)((r & 7)*16);
                uint32_t off = (uint32_t)(r*128) + kb;
                ldmatrix_x4(ah[m], sAh + off);
                ldmatrix_x4(al[m], sAl + off);
            }
#pragma unroll
            for (int n = 0; n < 4; n++) {
                int nr = wn + n*8 + b_r;
                uint32_t kb = (uint32_t)(ks*32 + b_s) ^ (uint32_t)((nr & 7)*16);
                uint32_t off = (uint32_t)(nr*128) + kb;
                uint32_t bh[2], bl[2];
                ldmatrix_x2(bh, sBh + off);
                ldmatrix_x2(bl, sBl + off);
#pragma unroll
                for (int m = 0; m < 4; m++) {
                    mma_bf16(acc[m][n], ah[m], bh);
                    mma_bf16(acc[m][n], ah[m], bl);
                    mma_bf16(acc[m][n], al[m], bh);
                }
            }
        }
        __syncthreads();
    }

    const int cr = lane >> 2;
    const int cc = (lane & 3) * 2;
#pragma unroll
    for (int m = 0; m < 4; m++) {
        int r = row0 + wm + m*16 + cr;
#pragma unroll
        for (int n = 0; n < 4; n++) {
            int col = wn + n*8 + cc;
            *(float2*)&C[(size_t)r*NK + col]       = make_float2(acc[m][n][0], acc[m][n][1]);
            *(float2*)&C[(size_t)(r + 8)*NK + col] = make_float2(acc[m][n][2], acc[m][n][3]);
        }
    }
}

// ---------------- 3) x_spec partial: evecs^T @ (x*mass), split-K ------------
__global__ __launch_bounds__(256) void k_spec(const float* __restrict__ evecs,
                                              const float* __restrict__ mass) {
    const int s = blockIdx.x, b = blockIdx.y;
    const float* E = evecs + (size_t)b*NV*NK;
    const float* X = g_x   + (size_t)b*NV*NC;
    const float* M = mass  + (size_t)b*NV;

    __shared__ float Es[8][128];
    __shared__ float Xs[8][128];

    const int tid = threadIdx.x;
    const int tx = tid & 15, ty = tid >> 4;
    const int lrow = tid >> 5;
    const int lcol = (tid & 31) * 4;
    const int v0 = s * (NV / NSPLIT);

    float acc[8][8] = {};

    for (int vt = 0; vt < NV/NSPLIT; vt += 8) {
        int vb = v0 + vt + lrow;
        *(float4*)&Es[lrow][lcol] = *(const float4*)&E[(size_t)vb*NK + lcol];
        float4 xv = *(const float4*)&X[(size_t)vb*NC + lcol];
        float mv = M[vb];
        xv.x *= mv; xv.y *= mv; xv.z *= mv; xv.w *= mv;
        *(float4*)&Xs[lrow][lcol] = xv;
        __syncthreads();
#pragma unroll
        for (int vv = 0; vv < 8; vv++) {
            float e[8], xr[8];
#pragma unroll
            for (int i = 0; i < 8; i++) e[i]  = Es[vv][ty*8+i];
#pragma unroll
            for (int j = 0; j < 8; j++) xr[j] = Xs[vv][tx*8+j];
#pragma unroll
            for (int i = 0; i < 8; i++)
#pragma unroll
                for (int j = 0; j < 8; j++)
                    acc[i][j] = fmaf(e[i], xr[j], acc[i][j]);
        }
        __syncthreads();
    }
    float* P = g_specp + ((size_t)(s*BQ + b)*NK)*NC;
#pragma unroll
    for (int i = 0; i < 8; i++)
#pragma unroll
        for (int j = 0; j < 8; j += 4) {
            float4 v = make_float4(acc[i][j], acc[i][j+1], acc[i][j+2], acc[i][j+3]);
            *(float4*)&P[(size_t)(ty*8+i)*NC + tx*8 + j] = v;
        }
}

// ---------------- 4) reduce partials + diffusion coefficients ---------------
__global__ __launch_bounds__(256) void k_scale(const float* __restrict__ evals,
                                               const float* __restrict__ t, int iblk) {
    int idx = blockIdx.x * blockDim.x + threadIdx.x;
    int c = idx & 127;
    int k = (idx >> 7) & 127;
    int b = idx >> 14;
    float ti = fmaxf(t[iblk*NC + c], 1e-8f);
    float coef = expf(-evals[b*NK + k] * ti);
    float ssum = 0.f;
#pragma unroll
    for (int p = 0; p < NSPLIT; p++)
        ssum += g_specp[((size_t)(p*BQ + b)*NK + k)*NC + c];
    g_y[idx] = coef * ssum;
}

// ---------------- 5) fused grad features ------------------------------------
#define GF_SMEM_FLOATS (2*128*65 + 2*16*64 + 2*16*128)
#define GF_SMEM_BYTES  (GF_SMEM_FLOATS*4)

__global__ __launch_bounds__(256, 1) void k_grad_feat(const float* __restrict__ Are,
                                                      const float* __restrict__ Aim,
                                                      int iblk) {
    extern __shared__ float sm[];
    float* gxT  = sm;                        // [128][65]  (channel-major)
    float* gyT  = sm + 128*65;
    float* AsT  = sm + 2*128*65;             // [16][64]
    float* AsT2 = AsT + 16*64;
    float* WsA  = AsT2 + 16*64;              // [16][128]
    float* WsB  = WsA + 16*128;

    const int b = blockIdx.y;
    const int row0 = blockIdx.x * 64;
    const int tid = threadIdx.x;
    const int tc = tid & 31, tr = tid >> 5;
    const int larow = tid >> 2, lacol = (tid & 3) * 4;

    const float* AX = g_GXe + (size_t)b*NV*NK;
    const float* AY = g_GYe + (size_t)b*NV*NK;
    const float* Y  = g_y   + (size_t)b*NK*NC;

    // ---- phase 1: gx, gy (two accumulator sets, shared Ws=y chunk) ----
    float accx[8][4] = {}, accy[8][4] = {};
    for (int k0 = 0; k0 < 128; k0 += 16) {
        float4 avx = *(const float4*)&AX[(size_t)(row0 + larow)*NK + k0 + lacol];
        float4 avy = *(const float4*)&AY[(size_t)(row0 + larow)*NK + k0 + lacol];
        AsT [(lacol+0)*64 + larow] = avx.x; AsT [(lacol+1)*64 + larow] = avx.y;
        AsT [(lacol+2)*64 + larow] = avx.z; AsT [(lacol+3)*64 + larow] = avx.w;
        AsT2[(lacol+0)*64 + larow] = avy.x; AsT2[(lacol+1)*64 + larow] = avy.y;
        AsT2[(lacol+2)*64 + larow] = avy.z; AsT2[(lacol+3)*64 + larow] = avy.w;
#pragma unroll
        for (int l = 0; l < 2; l++) {
            int idx = tid + l*256;
            int r  = idx >> 5;
            int c4 = (idx & 31) * 4;
            *(float4*)&WsA[r*128 + c4] = *(const float4*)&Y[(size_t)(k0 + r)*NC + c4];
        }
        __syncthreads();
#pragma unroll
        for (int kk = 0; kk < 16; kk++) {
            float4 wv = *(const float4*)&WsA[kk*128 + tc*4];
#pragma unroll
            for (int r = 0; r < 8; r++) {
                float ax = AsT [kk*64 + tr*8 + r];
                float ay = AsT2[kk*64 + tr*8 + r];
                accx[r][0] = fmaf(ax, wv.x, accx[r][0]);
                accx[r][1] = fmaf(ax, wv.y, accx[r][1]);
                accx[r][2] = fmaf(ax, wv.z, accx[r][2]);
                accx[r][3] = fmaf(ax, wv.w, accx[r][3]);
                accy[r][0] = fmaf(ay, wv.x, accy[r][0]);
                accy[r][1] = fmaf(ay, wv.y, accy[r][1]);
                accy[r][2] = fmaf(ay, wv.z, accy[r][2]);
                accy[r][3] = fmaf(ay, wv.w, accy[r][3]);
            }
        }
        __syncthreads();
    }
#pragma unroll
    for (int r = 0; r < 8; r++)
#pragma unroll
        for (int j = 0; j < 4; j++) {
            gxT[(tc*4+j)*65 + tr*8 + r] = accx[r][j];
            gyT[(tc*4+j)*65 + tr*8 + r] = accy[r][j];
        }
    __syncthreads();

    // ---- phase 2: br, bi against Are/Aim; epilogue tanh -> gfeat ----
    const float* ar_p = Are + (size_t)iblk*128*128;
    const float* ai_p = Aim + (size_t)iblk*128*128;
    float accr[8][4] = {}, acci[8][4] = {};
    for (int k0 = 0; k0 < 128; k0 += 16) {
#pragma unroll
        for (int l = 0; l < 2; l++) {
            int idx = tid + l*256;
            int r  = idx >> 5;
            int c4 = (idx & 31) * 4;
            *(float4*)&WsA[r*128 + c4] = *(const float4*)&ar_p[(size_t)(k0 + r)*128 + c4];
            *(float4*)&WsB[r*128 + c4] = *(const float4*)&ai_p[(size_t)(k0 + r)*128 + c4];
        }
        __syncthreads();
#pragma unroll
        for (int kk = 0; kk < 16; kk++) {
            float4 ar = *(const float4*)&WsA[kk*128 + tc*4];
            float4 ai = *(const float4*)&WsB[kk*128 + tc*4];
#pragma unroll
            for (int r = 0; r < 8; r++) {
                float gx = gxT[(k0+kk)*65 + tr*8 + r];
                float gy = gyT[(k0+kk)*65 + tr*8 + r];
                accr[r][0] = fmaf(gx, ar.x, accr[r][0]); accr[r][0] = fmaf(-gy, ai.x, accr[r][0]);
                accr[r][1] = fmaf(gx, ar.y, accr[r][1]); accr[r][1] = fmaf(-gy, ai.y, accr[r][1]);
                accr[r][2] = fmaf(gx, ar.z, accr[r][2]); accr[r][2] = fmaf(-gy, ai.z, accr[r][2]);
                accr[r][3] = fmaf(gx, ar.w, accr[r][3]); accr[r][3] = fmaf(-gy, ai.w, accr[r][3]);
                acci[r][0] = fmaf(gy, ar.x, acci[r][0]); acci[r][0] = fmaf( gx, ai.x, acci[r][0]);
                acci[r][1] = fmaf(gy, ar.y, acci[r][1]); acci[r][1] = fmaf( gx, ai.y, acci[r][1]);
                acci[r][2] = fmaf(gy, ar.z, acci[r][2]); acci[r][2] = fmaf( gx, ai.z, acci[r][2]);
                acci[r][3] = fmaf(gy, ar.w, acci[r][3]); acci[r][3] = fmaf( gx, ai.w, acci[r][3]);
            }
        }
        __syncthreads();
    }
    float* GF = g_gfeat + (size_t)b*NV*NC;
#pragma unroll
    for (int r = 0; r < 8; r++) {
        int row = row0 + tr*8 + r;
        float4 v;
        float gx0 = gxT[(tc*4+0)*65 + tr*8 + r], gy0 = gyT[(tc*4+0)*65 + tr*8 + r];
        float gx1 = gxT[(tc*4+1)*65 + tr*8 + r], gy1 = gyT[(tc*4+1)*65 + tr*8 + r];
        float gx2 = gxT[(tc*4+2)*65 + tr*8 + r], gy2 = gyT[(tc*4+2)*65 + tr*8 + r];
        float gx3 = gxT[(tc*4+3)*65 + tr*8 + r], gy3 = gyT[(tc*4+3)*65 + tr*8 + r];
        v.x = tanhf(gx0*accr[r][0] + gy0*acci[r][0]);
        v.y = tanhf(gx1*accr[r][1] + gy1*acci[r][1]);
        v.z = tanhf(gx2*accr[r][2] + gy2*acci[r][2]);
        v.w = tanhf(gx3*accr[r][3] + gy3*acci[r][3]);
        *(float4*)&GF[(size_t)row*NC + tc*4] = v;
    }
}

// ---------------- 6) fused xdiff + 3-layer MLP + residual -------------------
#define MLP_SMEM_FLOATS (3*128*65 + 16*64 + 16*128)
#define MLP_SMEM_BYTES  (MLP_SMEM_FLOATS*4)

__global__ __launch_bounds__(256, 1) void k_mlp(const float* __restrict__ evecs,
                                                const float* __restrict__ W0,
                                                const float* __restrict__ b0,
                                                const float* __restrict__ W1,
                                                const float* __restrict__ b1,
                                                const float* __restrict__ W2,
                                                const float* __restrict__ b2,
                                                int iblk) {
    extern __shared__ float sm[];
    float* xdT = sm;                 // [128][65] channel-major xdiff tile
    float* h0T = sm + 128*65;
    float* h1T = sm + 2*128*65;
    float* AsT = sm + 3*128*65;      // [16][64]
    float* Ws  = AsT + 16*64;        // [16][128]

    const int b = blockIdx.y;
    const int row0 = blockIdx.x * 64;
    const int tid = threadIdx.x;
    const int tc = tid & 31, tr = tid >> 5;
    const int larow = tid >> 2, lacol = (tid & 3) * 4;

    const float* Y = g_y + (size_t)b*NK*NC;

    // ---- phase 0: xdiff = evecs @ y ----
    {
        const float* A = evecs + (size_t)b*NV*NK;
        float acc[8][4] = {};
        for (int k0 = 0; k0 < 128; k0 += 16) {
            float4 av = *(const float4*)&A[(size_t)(row0 + larow)*NK + k0 + lacol];
            AsT[(lacol+0)*64 + larow] = av.x; AsT[(lacol+1)*64 + larow] = av.y;
            AsT[(lacol+2)*64 + larow] = av.z; AsT[(lacol+3)*64 + larow] = av.w;
#pragma unroll
            for (int l = 0; l < 2; l++) {
                int idx = tid + l*256;
                int r  = idx >> 5;
                int c4 = (idx & 31) * 4;
                *(float4*)&Ws[r*128 + c4] = *(const float4*)&Y[(size_t)(k0 + r)*NC + c4];
            }
            __syncthreads();
#pragma unroll
            for (int kk = 0; kk < 16; kk++) {
                float4 wv = *(const float4*)&Ws[kk*128 + tc*4];
#pragma unroll
                for (int r = 0; r < 8; r++) {
                    float a = AsT[kk*64 + tr*8 + r];
                    acc[r][0] = fmaf(a, wv.x, acc[r][0]);
                    acc[r][1] = fmaf(a, wv.y, acc[r][1]);
                    acc[r][2] = fmaf(a, wv.z, acc[r][2]);
                    acc[r][3] = fmaf(a, wv.w, acc[r][3]);
                }
            }
            __syncthreads();
        }
#pragma unroll
        for (int r = 0; r < 8; r++)
#pragma unroll
            for (int j = 0; j < 4; j++)
                xdT[(tc*4+j)*65 + tr*8 + r] = acc[r][j];
        __syncthreads();
    }

    // ---- phase 1: h0 = relu(concat @ W0 + b0), K = 384 in 3 chunks ----
    {
        const float* W0i = W0 + (size_t)iblk*384*128;
        float acc[8][4] = {};
        for (int ci = 0; ci < 3; ci++) {
            const float* Ag = (ci == 0) ? g_x + (size_t)b*NV*NC
                                        : g_gfeat + (size_t)b*NV*NC;   // ci==2
            const float* Wc = W0i + (size_t)ci*128*128;
            for (int k0 = 0; k0 < 128; k0 += 16) {
                if (ci != 1) {
                    float4 av = *(const float4*)&Ag[(size_t)(row0 + larow)*NC + k0 + lacol];
                    AsT[(lacol+0)*64 + larow] = av.x; AsT[(lacol+1)*64 + larow] = av.y;
                    AsT[(lacol+2)*64 + larow] = av.z; AsT[(lacol+3)*64 + larow] = av.w;
                }
#pragma unroll
                for (int l = 0; l < 2; l++) {
                    int idx = tid + l*256;
                    int r  = idx >> 5;
                    int c4 = (idx & 31) * 4;
                    *(float4*)&Ws[r*128 + c4] = *(const float4*)&Wc[(size_t)(k0 + r)*128 + c4];
                }
                __syncthreads();
#pragma unroll
                for (int kk = 0; kk < 16; kk++) {
                    float4 wv = *(const float4*)&Ws[kk*128 + tc*4];
#pragma unroll
                    for (int r = 0; r < 8; r++) {
                        float a = (ci == 1) ? xdT[(k0+kk)*65 + tr*8 + r]
                                            : AsT[kk*64 + tr*8 + r];
                        acc[r][0] = fmaf(a, wv.x, acc[r][0]);
                        acc[r][1] = fmaf(a, wv.y, acc[r][1]);
                        acc[r][2] = fmaf(a, wv.z, acc[r][2]);
                        acc[r][3] = fmaf(a, wv.w, acc[r][3]);
                    }
                }
                __syncthreads();
            }
        }
        float4 bv = *(const float4*)&b0[iblk*128 + tc*4];
#pragma unroll
        for (int r = 0; r < 8; r++) {
            h0T[(tc*4+0)*65 + tr*8 + r] = fmaxf(acc[r][0] + bv.x, 0.f);
            h0T[(tc*4+1)*65 + tr*8 + r] = fmaxf(acc[r][1] + bv.y, 0.f);
            h0T[(tc*4+2)*65 + tr*8 + r] = fmaxf(acc[r][2] + bv.z, 0.f);
            h0T[(tc*4+3)*65 + tr*8 + r] = fmaxf(acc[r][3] + bv.w, 0.f);
        }
        __syncthreads();
    }

    // ---- phase 2: h1 = relu(h0 @ W1 + b1) ----
    {
        const float* W1i = W1 + (size_t)iblk*128*128;
        float acc[8][4] = {};
        for (int k0 = 0; k0 < 128; k0 += 16) {
#pragma unroll
            for (int l = 0; l < 2; l++) {
                int idx = tid + l*256;
                int r  = idx >> 5;
                int c4 = (idx & 31) * 4;
                *(float4*)&Ws[r*128 + c4] = *(const float4*)&W1i[(size_t)(k0 + r)*128 + c4];
            }
            __syncthreads();
#pragma unroll
            for (int kk = 0; kk < 16; kk++) {
                float4 wv = *(const float4*)&Ws[kk*128 + tc*4];
#pragma unroll
                for (int r = 0; r < 8; r++) {
                    float a = h0T[(k0+kk)*65 + tr*8 + r];
                    acc[r][0] = fmaf(a, wv.x, acc[r][0]);
                    acc[r][1] = fmaf(a, wv.y, acc[r][1]);
                    acc[r][2] = fmaf(a, wv.z, acc[r][2]);
                    acc[r][3] = fmaf(a, wv.w, acc[r][3]);
                }
            }
            __syncthreads();
        }
        float4 bv = *(const float4*)&b1[iblk*128 + tc*4];
#pragma unroll
        for (int r = 0; r < 8; r++) {
            h1T[(tc*4+0)*65 + tr*8 + r] = fmaxf(acc[r][0] + bv.x, 0.f);
            h1T[(tc*4+1)*65 + tr*8 + r] = fmaxf(acc[r][1] + bv.y, 0.f);
            h1T[(tc*4+2)*65 + tr*8 + r] = fmaxf(acc[r][2] + bv.z, 0.f);
            h1T[(tc*4+3)*65 + tr*8 + r] = fmaxf(acc[r][3] + bv.w, 0.f);
        }
        __syncthreads();
    }

    // ---- phase 3: x += h1 @ W2 + b2 ----
    {
        const float* W2i = W2 + (size_t)iblk*128*128;
        float acc[8][4] = {};
        for (int k0 = 0; k0 < 128; k0 += 16) {
#pragma unroll
            for (int l = 0; l < 2; l++) {
                int idx = tid + l*256;
                int r  = idx >> 5;
                int c4 = (idx & 31) * 4;
                *(float4*)&Ws[r*128 + c4] = *(const float4*)&W2i[(size_t)(k0 + r)*128 + c4];
            }
            __syncthreads();
#pragma unroll
            for (int kk = 0; kk < 16; kk++) {
                float4 wv = *(const float4*)&Ws[kk*128 + tc*4];
#pragma unroll
                for (int r = 0; r < 8; r++) {
                    float a = h1T[(k0+kk)*65 + tr*8 + r];
                    acc[r][0] = fmaf(a, wv.x, acc[r][0]);
                    acc[r][1] = fmaf(a, wv.y, acc[r][1]);
                    acc[r][2] = fmaf(a, wv.z, acc[r][2]);
                    acc[r][3] = fmaf(a, wv.w, acc[r][3]);
                }
            }
            __syncthreads();
        }
        float4 bv = *(const float4*)&b2[iblk*128 + tc*4];
        float* X = g_x + (size_t)b*NV*NC;
#pragma unroll
        for (int r = 0; r < 8; r++) {
            int row = row0 + tr*8 + r;
            float4 xv = *(const float4*)&X[(size_t)row*NC + tc*4];
            xv.x += acc[r][0] + bv.x;
            xv.y += acc[r][1] + bv.y;
            xv.z += acc[r][2] + bv.z;
            xv.w += acc[r][3] + bv.w;
            *(float4*)&X[(size_t)row*NC + tc*4] = xv;
        }
    }
}

// ---------------- 7) generic GEMM (final output only) -----------------------
__global__ __launch_bounds__(256) void k_gemm(const float* A0,
                                              long long strideA,
                                              const float* __restrict__ W,
                                              const float* __restrict__ bias,
                                              float* C, long long strideC) {
    const int b = blockIdx.y;
    const int row0 = blockIdx.x * 64;

    __shared__ float AsT[16][64];
    __shared__ float Ws[16][128];

    const int tid = threadIdx.x;
    const int tc = tid & 31, tr = tid >> 5;
    const int larow = tid >> 2;
    const int lacol = (tid & 3) * 4;

    float acc[8][4] = {};
    const float* A = A0 + (size_t)b * strideA;

    for (int k0 = 0; k0 < 128; k0 += 16) {
        float4 av = *(const float4*)&A[(size_t)(row0 + larow)*128 + k0 + lacol];
        AsT[lacol+0][larow] = av.x; AsT[lacol+1][larow] = av.y;
        AsT[lacol+2][larow] = av.z; AsT[lacol+3][larow] = av.w;
#pragma unroll
        for (int l = 0; l < 2; l++) {
            int idx = tid + l*256;
            int r  = idx >> 5;
            int c4 = (idx & 31) * 4;
            *(float4*)&Ws[r][c4] = *(const float4*)&W[(size_t)(k0 + r)*128 + c4];
        }
        __syncthreads();
#pragma unroll
        for (int kk = 0; kk < 16; kk++) {
            float4 wv = *(const float4*)&Ws[kk][tc*4];
#pragma unroll
            for (int r = 0; r < 8; r++) {
                float a = AsT[kk][tr*8 + r];
                acc[r][0] = fmaf(a, wv.x, acc[r][0]);
                acc[r][1] = fmaf(a, wv.y, acc[r][1]);
                acc[r][2] = fmaf(a, wv.z, acc[r][2]);
                acc[r][3] = fmaf(a, wv.w, acc[r][3]);
            }
        }
        __syncthreads();
    }
    float4 bv = *(const float4*)&bias[tc*4];
#pragma unroll
    for (int r = 0; r < 8; r++) {
        int row = row0 + tr*8 + r;
        float4 v = make_float4(acc[r][0] + bv.x, acc[r][1] + bv.y,
                               acc[r][2] + bv.z, acc[r][3] + bv.w);
        *(float4*)&C[(size_t)b*strideC + (size_t)row*128 + tc*4] = v;
    }
}

// ---------------- host orchestration ---------------------------------------
extern "C" void kernel_launch(void* const* d_in, const int* in_sizes, int n_in,
                              void* d_out, int out_size) {
    const float* x_in  = (const float*)d_in[0];
    const float* mass  = (const float*)d_in[1];
    const float* evals = (const float*)d_in[2];
    const float* evecs = (const float*)d_in[3];
    const float* gradX = (const float*)d_in[4];
    const float* gradY = (const float*)d_in[5];
    const float* Wf    = (const float*)d_in[6];
    const float* bf    = (const float*)d_in[7];
    const float* Wl    = (const float*)d_in[8];
    const float* bl    = (const float*)d_in[9];
    const float* t     = (const float*)d_in[10];
    const float* Are   = (const float*)d_in[11];
    const float* Aim   = (const float*)d_in[12];
    const float* W0    = (const float*)d_in[13];
    const float* b0    = (const float*)d_in[14];
    const float* W1    = (const float*)d_in[15];
    const float* b1    = (const float*)d_in[16];
    const float* W2    = (const float*)d_in[17];
    const float* b2    = (const float*)d_in[18];
    float* out = (float*)d_out;

    float* p_x;
    cudaGetSymbolAddress((void**)&p_x, g_x);

    cudaFuncSetAttribute(k_grad_mma, cudaFuncAttributeMaxDynamicSharedMemorySize, GM_SMEM);
    cudaFuncSetAttribute(k_grad_feat, cudaFuncAttributeMaxDynamicSharedMemorySize, GF_SMEM_BYTES);
    cudaFuncSetAttribute(k_mlp, cudaFuncAttributeMaxDynamicSharedMemorySize, MLP_SMEM_BYTES);

    const long long sVC = (long long)NV * NC;

    // x = x_in @ Wf + bf
    k_input<<<BQ*NV, 128>>>(x_in, Wf, bf);

    // evecs^T bf16 hi/lo split, then HMMA GXe/GYe = grad @ evecs
    k_evT<<<dim3(NV/32, NK/32, BQ), dim3(32, 8)>>>(evecs);
    k_grad_mma<<<dim3(NV/128, BQ, 2), 256, GM_SMEM>>>(gradX, gradY);

    for (int i = 0; i < 4; i++) {
        k_spec<<<dim3(NSPLIT, BQ), 256>>>(evecs, mass);
        k_scale<<<(BQ*NK*NC)/256, 256>>>(evals, t, i);
        k_grad_feat<<<dim3(NV/64, BQ), 256, GF_SMEM_BYTES>>>(Are, Aim, i);
        k_mlp<<<dim3(NV/64, BQ), 256, MLP_SMEM_BYTES>>>(evecs, W0, b0, W1, b1, W2, b2, i);
    }

    // out = x @ Wl + bl
    k_gemm<<<dim3(NV/64, BQ), 256>>>(p_x, sVC, Wl, bl, out, sVC);
}